// round 11
// baseline (speedup 1.0000x reference)
#include <cuda_runtime.h>
#include <cuda_bf16.h>
#include <math.h>
#include <stdint.h>

typedef unsigned int uint32;

#define NNODES 50000
#define NEDGES 800000
#define CH 128
#define TWOH 256
#define NLAYERS 5
#define NGRAPHS 256
#define OUTC 10
#define BN_EPS 1e-5f
#define MAXDEG 96

// ---------------- scratch (static device memory; no allocations) ----------------
__device__ int   g_cur[NNODES];
__device__ int   g_srcBuck[(size_t)NNODES * MAXDEG];

__device__ __nv_bfloat16 g_ah[(size_t)NNODES * CH];    // GIN input (x+agg) hi
__device__ __nv_bfloat16 g_al[(size_t)NNODES * CH];    // lo
__device__ __nv_bfloat16 g_bh[(size_t)NNODES * TWOH];  // hidden (after MLP1) hi
__device__ __nv_bfloat16 g_bl[(size_t)NNODES * TWOH];  // lo
__device__ float g_x[(size_t)NNODES * CH];             // layer output fp32

// weights, transposed to [n][k] and split hi/lo
__device__ __nv_bfloat16 g_w1h[NLAYERS * TWOH * CH];   // [l][n=256][k=128]
__device__ __nv_bfloat16 g_w1l[NLAYERS * TWOH * CH];
__device__ __nv_bfloat16 g_w2h[NLAYERS * CH * TWOH];   // [l][n=128][k=256]
__device__ __nv_bfloat16 g_w2l[NLAYERS * CH * TWOH];

// ---------------- prep: zero bucket counters + transpose/split weights ----------------
__global__ void k_prep(const float* __restrict__ W1, const float* __restrict__ W2) {
    int t = blockIdx.x * blockDim.x + threadIdx.x;
    if (t < NNODES) g_cur[t] = 0;
    const int S = NLAYERS * TWOH * CH;
    if (t < S) {
        int l = t / (TWOH * CH);
        int r = t % (TWOH * CH);
        int n = r / CH;
        int k = r % CH;
        float v = W1[(size_t)l * CH * TWOH + (size_t)k * TWOH + n];
        __nv_bfloat16 h = __float2bfloat16(v);
        g_w1h[t] = h;
        g_w1l[t] = __float2bfloat16(v - __bfloat162float(h));
    } else if (t < 2 * S) {
        int t2 = t - S;
        int l = t2 / (CH * TWOH);
        int r = t2 % (CH * TWOH);
        int n = r / TWOH;
        int k = r % TWOH;
        float v = W2[(size_t)l * TWOH * CH + (size_t)k * CH + n];
        __nv_bfloat16 h = __float2bfloat16(v);
        g_w2h[t2] = h;
        g_w2l[t2] = __float2bfloat16(v - __bfloat162float(h));
    }
}

// ---------------- bucket scatter: one pass over edges ----------------
__global__ void k_fill(const int* __restrict__ ei) {
    int t = blockIdx.x * blockDim.x + threadIdx.x;
    if (t < NEDGES) {
        int s = ei[t];
        int d = ei[NEDGES + t];
        int pos = atomicAdd(&g_cur[d], 1);
        if (pos < MAXDEG) g_srcBuck[(size_t)d * MAXDEG + pos] = s;
    }
}

// ---------------- aggregation: one warp/node, fp32 accum, writes bf16 hi/lo ----------------
template<int USE_EXT>
__global__ void k_agg(const float* __restrict__ xext) {
    int warp = (blockIdx.x * blockDim.x + threadIdx.x) >> 5;
    int lane = threadIdx.x & 31;
    if (warp >= NNODES) return;
    const float* xin = USE_EXT ? xext : (const float*)g_x;
    int deg = g_cur[warp];
    if (deg > MAXDEG) deg = MAXDEG;
    const int* buck = g_srcBuck + (size_t)warp * MAXDEG;
    float4 acc = *((const float4*)(xin + (size_t)warp * CH) + lane);
    for (int e = 0; e < deg; e++) {
        int s = buck[e];
        float4 v = *((const float4*)(xin + (size_t)s * CH) + lane);
        acc.x += v.x; acc.y += v.y; acc.z += v.z; acc.w += v.w;
    }
    float vv[4] = {acc.x, acc.y, acc.z, acc.w};
    __nv_bfloat162 hp[2], lp[2];
    #pragma unroll
    for (int j = 0; j < 2; j++) {
        __nv_bfloat16 h0 = __float2bfloat16(vv[2*j]);
        __nv_bfloat16 h1 = __float2bfloat16(vv[2*j+1]);
        hp[j] = __nv_bfloat162(h0, h1);
        lp[j] = __nv_bfloat162(__float2bfloat16(vv[2*j]   - __bfloat162float(h0)),
                               __float2bfloat16(vv[2*j+1] - __bfloat162float(h1)));
    }
    __nv_bfloat162* ph = (__nv_bfloat162*)(g_ah + (size_t)warp * CH) + lane * 2;
    __nv_bfloat162* pl = (__nv_bfloat162*)(g_al + (size_t)warp * CH) + lane * 2;
    ph[0] = hp[0]; ph[1] = hp[1];
    pl[0] = lp[0]; pl[1] = lp[1];
}

// ---------------- tensor-core GEMM (bf16 split, fp32 accum) + bias/BN/ReLU ----------------
// 128-thread blocks, 4 warps in 2x2; warp tile M64 x N64. Block tile M128 x N128.
#define SSTR 40   // smem row stride in bf16 (80 bytes): 16B-aligned & LDSM conflict-free

__device__ __forceinline__ void mma_bf16(float c[4], const uint32 a[4], const uint32 b0, const uint32 b1) {
    asm volatile(
        "mma.sync.aligned.m16n8k16.row.col.f32.bf16.bf16.f32 "
        "{%0,%1,%2,%3}, {%4,%5,%6,%7}, {%8,%9}, {%0,%1,%2,%3};"
        : "+f"(c[0]), "+f"(c[1]), "+f"(c[2]), "+f"(c[3])
        : "r"(a[0]), "r"(a[1]), "r"(a[2]), "r"(a[3]), "r"(b0), "r"(b1));
}

__device__ __forceinline__ void ldsm_x4(uint32& r0, uint32& r1, uint32& r2, uint32& r3, uint32 addr) {
    asm volatile("ldmatrix.sync.aligned.m8n8.x4.shared.b16 {%0,%1,%2,%3}, [%4];"
                 : "=r"(r0), "=r"(r1), "=r"(r2), "=r"(r3) : "r"(addr));
}

__device__ __forceinline__ void cp16(uint32 saddr, const void* gptr, uint32 src_sz) {
    asm volatile("cp.async.cg.shared.global [%0], [%1], 16, %2;"
                 :: "r"(saddr), "l"(gptr), "r"(src_sz) : "memory");
}

template<int K, int NCOL, int SEL>
__global__ void __launch_bounds__(128)
k_mmagemm(int layer,
          const float* __restrict__ bias, const float* __restrict__ gam,
          const float* __restrict__ bet, const float* __restrict__ mu,
          const float* __restrict__ var)
{
    const __nv_bfloat16* Ah = SEL ? g_bh : g_ah;
    const __nv_bfloat16* Al = SEL ? g_bl : g_al;
    const __nv_bfloat16* Wh = SEL ? (g_w2h + (size_t)layer * CH * TWOH)
                                  : (g_w1h + (size_t)layer * TWOH * CH);
    const __nv_bfloat16* Wl = SEL ? (g_w2l + (size_t)layer * CH * TWOH)
                                  : (g_w1l + (size_t)layer * TWOH * CH);

    __shared__ __nv_bfloat16 sAh[128 * SSTR];
    __shared__ __nv_bfloat16 sAl[128 * SSTR];
    __shared__ __nv_bfloat16 sBh[128 * SSTR];
    __shared__ __nv_bfloat16 sBl[128 * SSTR];

    int tid = threadIdx.x;
    int warp = tid >> 5, lane = tid & 31;
    int wm = warp & 1;        // 2 warps along M: 64 rows each
    int wn = warp >> 1;       // 2 warps along N: 64 cols each
    int row0 = blockIdx.x * 128;
    int col0 = blockIdx.y * 128;
    int g = lane >> 2, q = lane & 3;

    // LDSM address components (element offsets)
    int a_off = (wm * 64 + (lane & 7) + ((lane >> 3) & 1) * 8) * SSTR + (lane >> 4) * 8;
    int b_off = (wn * 64 + (lane & 7) + (lane >> 4) * 8) * SSTR + ((lane >> 3) & 1) * 8;

    uint32 sAh_u = (uint32)__cvta_generic_to_shared(sAh);
    uint32 sAl_u = (uint32)__cvta_generic_to_shared(sAl);
    uint32 sBh_u = (uint32)__cvta_generic_to_shared(sBh);
    uint32 sBl_u = (uint32)__cvta_generic_to_shared(sBl);

    float c[4][8][4];
    #pragma unroll
    for (int i = 0; i < 4; i++)
        #pragma unroll
        for (int j = 0; j < 8; j++)
            #pragma unroll
            for (int r = 0; r < 4; r++) c[i][j][r] = 0.f;

    // global row for this thread's smem row (thread t owns smem row t, 4 chunks of 8 bf16)
    int grA = row0 + tid;
    uint32 aok = (grA < NNODES) ? 16u : 0u;
    const __nv_bfloat16* gAh = Ah + (size_t)grA * K;
    const __nv_bfloat16* gAl = Al + (size_t)grA * K;
    const __nv_bfloat16* gWh = Wh + (size_t)(col0 + tid) * K;
    const __nv_bfloat16* gWl = Wl + (size_t)(col0 + tid) * K;
    uint32 srow = (uint32)(tid * SSTR) * 2u;   // byte offset of this thread's smem row

    for (int kk = 0; kk < K; kk += 32) {
        #pragma unroll
        for (int i = 0; i < 4; i++) {
            uint32 soff = srow + i * 16u;
            cp16(sAh_u + soff, gAh + kk + i * 8, aok);
            cp16(sAl_u + soff, gAl + kk + i * 8, aok);
            cp16(sBh_u + soff, gWh + kk + i * 8, 16u);
            cp16(sBl_u + soff, gWl + kk + i * 8, 16u);
        }
        asm volatile("cp.async.commit_group;" ::: "memory");
        asm volatile("cp.async.wait_group 0;" ::: "memory");
        __syncthreads();

        #pragma unroll
        for (int ks = 0; ks < 32; ks += 16) {
            uint32 ah[4][4], al4[4][4];
            #pragma unroll
            for (int mt = 0; mt < 4; mt++) {
                uint32 eoff = (uint32)(a_off + mt * 16 * SSTR + ks) * 2u;
                ldsm_x4(ah[mt][0], ah[mt][1], ah[mt][2], ah[mt][3], sAh_u + eoff);
                ldsm_x4(al4[mt][0], al4[mt][1], al4[mt][2], al4[mt][3], sAl_u + eoff);
            }
            #pragma unroll
            for (int p = 0; p < 4; p++) {
                uint32 eoff = (uint32)(b_off + p * 16 * SSTR + ks) * 2u;
                uint32 bh0, bh1, bh2, bh3, bl0, bl1, bl2, bl3;
                ldsm_x4(bh0, bh1, bh2, bh3, sBh_u + eoff);
                ldsm_x4(bl0, bl1, bl2, bl3, sBl_u + eoff);
                #pragma unroll
                for (int mt = 0; mt < 4; mt++) {
                    mma_bf16(c[mt][2*p],     ah[mt],  bh0, bh1);
                    mma_bf16(c[mt][2*p],     ah[mt],  bl0, bl1);
                    mma_bf16(c[mt][2*p],     al4[mt], bh0, bh1);
                    mma_bf16(c[mt][2*p + 1], ah[mt],  bh2, bh3);
                    mma_bf16(c[mt][2*p + 1], ah[mt],  bl2, bl3);
                    mma_bf16(c[mt][2*p + 1], al4[mt], bh2, bh3);
                }
            }
        }
        __syncthreads();
    }

    // epilogue: bias + BN + relu
    float sc[8][2], sh[8][2];
    #pragma unroll
    for (int nt = 0; nt < 8; nt++) {
        #pragma unroll
        for (int j = 0; j < 2; j++) {
            int col = col0 + wn * 64 + nt * 8 + 2 * q + j;
            float s = gam[col] * rsqrtf(var[col] + BN_EPS);
            sc[nt][j] = s;
            sh[nt][j] = bet[col] - mu[col] * s + bias[col] * s;
        }
    }
    #pragma unroll
    for (int mt = 0; mt < 4; mt++) {
        int r0 = row0 + wm * 64 + mt * 16 + g;
        int r1 = r0 + 8;
        #pragma unroll
        for (int nt = 0; nt < 8; nt++) {
            int col = col0 + wn * 64 + nt * 8 + 2 * q;
            float v00 = fmaxf(c[mt][nt][0] * sc[nt][0] + sh[nt][0], 0.f);
            float v01 = fmaxf(c[mt][nt][1] * sc[nt][1] + sh[nt][1], 0.f);
            float v10 = fmaxf(c[mt][nt][2] * sc[nt][0] + sh[nt][0], 0.f);
            float v11 = fmaxf(c[mt][nt][3] * sc[nt][1] + sh[nt][1], 0.f);
            if (SEL == 0) {
                if (r0 < NNODES) {
                    __nv_bfloat16 h0 = __float2bfloat16(v00), h1 = __float2bfloat16(v01);
                    *(__nv_bfloat162*)(g_bh + (size_t)r0 * TWOH + col) = __nv_bfloat162(h0, h1);
                    *(__nv_bfloat162*)(g_bl + (size_t)r0 * TWOH + col) =
                        __nv_bfloat162(__float2bfloat16(v00 - __bfloat162float(h0)),
                                       __float2bfloat16(v01 - __bfloat162float(h1)));
                }
                if (r1 < NNODES) {
                    __nv_bfloat16 h0 = __float2bfloat16(v10), h1 = __float2bfloat16(v11);
                    *(__nv_bfloat162*)(g_bh + (size_t)r1 * TWOH + col) = __nv_bfloat162(h0, h1);
                    *(__nv_bfloat162*)(g_bl + (size_t)r1 * TWOH + col) =
                        __nv_bfloat162(__float2bfloat16(v10 - __bfloat162float(h0)),
                                       __float2bfloat16(v11 - __bfloat162float(h1)));
                }
            } else {
                if (r0 < NNODES) *(float2*)(g_x + (size_t)r0 * CH + col) = make_float2(v00, v01);
                if (r1 < NNODES) *(float2*)(g_x + (size_t)r1 * CH + col) = make_float2(v10, v11);
            }
        }
    }
}

// ---------------- fused pool + readout head (one block per graph, 128 threads) ----------------
__global__ void k_pool_head(const int* __restrict__ batch,
                            const float* __restrict__ Wl1, const float* __restrict__ bl1,
                            const float* __restrict__ gb1, const float* __restrict__ bb1,
                            const float* __restrict__ mb1, const float* __restrict__ vb1,
                            const float* __restrict__ Wl2, const float* __restrict__ bl2,
                            float* __restrict__ out)
{
    int gr = blockIdx.x;
    int t = threadIdx.x;   // 0..127 = channel

    int lo = 0, hi = NNODES;
    while (lo < hi) { int m = (lo + hi) >> 1; if (batch[m] < gr) lo = m + 1; else hi = m; }
    int start = lo;
    hi = NNODES;
    while (lo < hi) { int m = (lo + hi) >> 1; if (batch[m] < gr + 1) lo = m + 1; else hi = m; }
    int end = lo;

    float s0 = 0.f, s1 = 0.f;
    int i = start;
    for (; i + 1 < end; i += 2) {
        s0 += g_x[(size_t)i * CH + t];
        s1 += g_x[(size_t)(i + 1) * CH + t];
    }
    if (i < end) s0 += g_x[(size_t)i * CH + t];
    float pval = s0 + s1;

    __shared__ float p[CH];
    __shared__ float hrow[CH];
    __shared__ float logits[OUTC];
    p[t] = pval;
    __syncthreads();

    float acc = 0.f;
    #pragma unroll 8
    for (int k = 0; k < CH; k++) acc += p[k] * Wl1[k * CH + t];
    acc += bl1[t];
    float s = gb1[t] * rsqrtf(vb1[t] + BN_EPS);
    acc = (acc - mb1[t]) * s + bb1[t];
    hrow[t] = fmaxf(acc, 0.f);
    __syncthreads();
    if (t < OUTC) {
        float a = 0.f;
        #pragma unroll 8
        for (int k = 0; k < CH; k++) a += hrow[k] * Wl2[k * OUTC + t];
        logits[t] = a + bl2[t];
    }
    __syncthreads();
    if (t == 0) {
        float mx = -1e30f;
        for (int j = 0; j < OUTC; j++) mx = fmaxf(mx, logits[j]);
        float se = 0.f;
        for (int j = 0; j < OUTC; j++) se += expf(logits[j] - mx);
        float lse = mx + logf(se);
        for (int j = 0; j < OUTC; j++) out[gr * OUTC + j] = logits[j] - lse;
    }
}

// ---------------- launch ----------------
extern "C" void kernel_launch(void* const* d_in, const int* in_sizes, int n_in,
                              void* d_out, int out_size)
{
    const float* x     = (const float*)d_in[0];
    const int*   ei    = (const int*)d_in[1];
    const int*   batch = (const int*)d_in[2];
    const float* W1  = (const float*)d_in[3];
    const float* b1  = (const float*)d_in[4];
    const float* g1  = (const float*)d_in[5];
    const float* be1 = (const float*)d_in[6];
    const float* m1  = (const float*)d_in[7];
    const float* v1  = (const float*)d_in[8];
    const float* W2  = (const float*)d_in[9];
    const float* b2  = (const float*)d_in[10];
    const float* gO  = (const float*)d_in[11];
    const float* bO  = (const float*)d_in[12];
    const float* mO  = (const float*)d_in[13];
    const float* vO  = (const float*)d_in[14];
    const float* Wl1 = (const float*)d_in[15];
    const float* bl1 = (const float*)d_in[16];
    const float* gb1 = (const float*)d_in[17];
    const float* bb1 = (const float*)d_in[18];
    const float* mb1 = (const float*)d_in[19];
    const float* vb1 = (const float*)d_in[20];
    const float* Wl2 = (const float*)d_in[21];
    const float* bl2 = (const float*)d_in[22];
    float* out = (float*)d_out;

    k_prep<<<(2 * NLAYERS * TWOH * CH + 255) / 256, 256>>>(W1, W2);
    k_fill<<<(NEDGES + 255) / 256, 256>>>(ei);

    const int NBM = (NNODES + 127) / 128;   // 391
    for (int l = 0; l < NLAYERS; l++) {
        if (l == 0) k_agg<1><<<(NNODES * 32 + 255) / 256, 256>>>(x);
        else        k_agg<0><<<(NNODES * 32 + 255) / 256, 256>>>(nullptr);
        k_mmagemm<CH, TWOH, 0><<<dim3(NBM, 2), 128>>>(
            l, b1 + l * TWOH, g1 + l * TWOH, be1 + l * TWOH,
            m1 + l * TWOH, v1 + l * TWOH);
        k_mmagemm<TWOH, CH, 1><<<dim3(NBM, 1), 128>>>(
            l, b2 + l * CH, gO + l * CH, bO + l * CH,
            mO + l * CH, vO + l * CH);
    }

    k_pool_head<<<NGRAPHS, CH>>>(batch, Wl1, bl1, gb1, bb1, mb1, vb1, Wl2, bl2, out);
}

// round 12
// speedup vs baseline: 1.1324x; 1.1324x over previous
#include <cuda_runtime.h>
#include <cuda_bf16.h>
#include <math.h>
#include <stdint.h>

typedef unsigned int uint32;

#define NNODES 50000
#define NEDGES 800000
#define CH 128
#define TWOH 256
#define NLAYERS 5
#define NGRAPHS 256
#define OUTC 10
#define BN_EPS 1e-5f
#define MAXDEG 96

// ---------------- scratch (static device memory; no allocations) ----------------
__device__ int   g_cur[NNODES];
__device__ int   g_srcBuck[(size_t)NNODES * MAXDEG];

__device__ __nv_bfloat16 g_ah[(size_t)NNODES * CH];    // GIN input (x+agg) hi
__device__ __nv_bfloat16 g_al[(size_t)NNODES * CH];    // lo
__device__ __nv_bfloat16 g_bh[(size_t)NNODES * TWOH];  // hidden (after MLP1) hi
__device__ __nv_bfloat16 g_bl[(size_t)NNODES * TWOH];  // lo
__device__ float g_x[(size_t)NNODES * CH];             // layer output fp32

// weights, transposed to [n][k] and split hi/lo
__device__ __nv_bfloat16 g_w1h[NLAYERS * TWOH * CH];   // [l][n=256][k=128]
__device__ __nv_bfloat16 g_w1l[NLAYERS * TWOH * CH];
__device__ __nv_bfloat16 g_w2h[NLAYERS * CH * TWOH];   // [l][n=128][k=256]
__device__ __nv_bfloat16 g_w2l[NLAYERS * CH * TWOH];

// ---------------- prep: zero bucket counters + transpose/split weights ----------------
__global__ void k_prep(const float* __restrict__ W1, const float* __restrict__ W2) {
    int t = blockIdx.x * blockDim.x + threadIdx.x;
    if (t < NNODES) g_cur[t] = 0;
    const int S = NLAYERS * TWOH * CH;
    if (t < S) {
        int l = t / (TWOH * CH);
        int r = t % (TWOH * CH);
        int n = r / CH;
        int k = r % CH;
        float v = W1[(size_t)l * CH * TWOH + (size_t)k * TWOH + n];
        __nv_bfloat16 h = __float2bfloat16(v);
        g_w1h[t] = h;
        g_w1l[t] = __float2bfloat16(v - __bfloat162float(h));
    } else if (t < 2 * S) {
        int t2 = t - S;
        int l = t2 / (CH * TWOH);
        int r = t2 % (CH * TWOH);
        int n = r / TWOH;
        int k = r % TWOH;
        float v = W2[(size_t)l * TWOH * CH + (size_t)k * CH + n];
        __nv_bfloat16 h = __float2bfloat16(v);
        g_w2h[t2] = h;
        g_w2l[t2] = __float2bfloat16(v - __bfloat162float(h));
    }
}

// ---------------- bucket scatter: one pass over edges ----------------
__global__ void k_fill(const int* __restrict__ ei) {
    int t = blockIdx.x * blockDim.x + threadIdx.x;
    if (t < NEDGES) {
        int s = ei[t];
        int d = ei[NEDGES + t];
        int pos = atomicAdd(&g_cur[d], 1);
        if (pos < MAXDEG) g_srcBuck[(size_t)d * MAXDEG + pos] = s;
    }
}

// ---------------- aggregation: one warp/node, fp32 accum, writes bf16 hi/lo ----------------
template<int USE_EXT>
__global__ void k_agg(const float* __restrict__ xext) {
    int warp = (blockIdx.x * blockDim.x + threadIdx.x) >> 5;
    int lane = threadIdx.x & 31;
    if (warp >= NNODES) return;
    const float* xin = USE_EXT ? xext : (const float*)g_x;
    int deg = g_cur[warp];
    if (deg > MAXDEG) deg = MAXDEG;
    const int* buck = g_srcBuck + (size_t)warp * MAXDEG;
    float4 acc = *((const float4*)(xin + (size_t)warp * CH) + lane);
    for (int e = 0; e < deg; e++) {
        int s = buck[e];
        float4 v = *((const float4*)(xin + (size_t)s * CH) + lane);
        acc.x += v.x; acc.y += v.y; acc.z += v.z; acc.w += v.w;
    }
    float vv[4] = {acc.x, acc.y, acc.z, acc.w};
    __nv_bfloat162 hp[2], lp[2];
    #pragma unroll
    for (int j = 0; j < 2; j++) {
        __nv_bfloat16 h0 = __float2bfloat16(vv[2*j]);
        __nv_bfloat16 h1 = __float2bfloat16(vv[2*j+1]);
        hp[j] = __nv_bfloat162(h0, h1);
        lp[j] = __nv_bfloat162(__float2bfloat16(vv[2*j]   - __bfloat162float(h0)),
                               __float2bfloat16(vv[2*j+1] - __bfloat162float(h1)));
    }
    __nv_bfloat162* ph = (__nv_bfloat162*)(g_ah + (size_t)warp * CH) + lane * 2;
    __nv_bfloat162* pl = (__nv_bfloat162*)(g_al + (size_t)warp * CH) + lane * 2;
    ph[0] = hp[0]; ph[1] = hp[1];
    pl[0] = lp[0]; pl[1] = lp[1];
}

// ---------------- tensor-core GEMM (bf16 split, fp32 accum) + bias/BN/ReLU ----------------
// 256 threads, 8 warps (2 M x 4 N); warp tile M64 x N32; block tile M128 x N128.
// cp.async staging (no staging registers) + __launch_bounds__(256,2) -> 2 CTAs/SM.
#define SSTR 40   // smem row stride in bf16 (80 bytes): 16B-aligned & LDSM conflict-free

__device__ __forceinline__ void mma_bf16(float c[4], const uint32 a[4], const uint32 b[2]) {
    asm volatile(
        "mma.sync.aligned.m16n8k16.row.col.f32.bf16.bf16.f32 "
        "{%0,%1,%2,%3}, {%4,%5,%6,%7}, {%8,%9}, {%0,%1,%2,%3};"
        : "+f"(c[0]), "+f"(c[1]), "+f"(c[2]), "+f"(c[3])
        : "r"(a[0]), "r"(a[1]), "r"(a[2]), "r"(a[3]), "r"(b[0]), "r"(b[1]));
}

__device__ __forceinline__ void ldsm_x4(uint32& r0, uint32& r1, uint32& r2, uint32& r3, uint32 addr) {
    asm volatile("ldmatrix.sync.aligned.m8n8.x4.shared.b16 {%0,%1,%2,%3}, [%4];"
                 : "=r"(r0), "=r"(r1), "=r"(r2), "=r"(r3) : "r"(addr));
}

__device__ __forceinline__ void cp16(uint32 saddr, const void* gptr, uint32 src_sz) {
    asm volatile("cp.async.cg.shared.global [%0], [%1], 16, %2;"
                 :: "r"(saddr), "l"(gptr), "r"(src_sz) : "memory");
}

template<int K, int NCOL, int SEL>
__global__ void __launch_bounds__(256, 2)
k_mmagemm(int layer,
          const float* __restrict__ bias, const float* __restrict__ gam,
          const float* __restrict__ bet, const float* __restrict__ mu,
          const float* __restrict__ var)
{
    const __nv_bfloat16* Ah = SEL ? g_bh : g_ah;
    const __nv_bfloat16* Al = SEL ? g_bl : g_al;
    const __nv_bfloat16* Wh = SEL ? (g_w2h + (size_t)layer * CH * TWOH)
                                  : (g_w1h + (size_t)layer * TWOH * CH);
    const __nv_bfloat16* Wl = SEL ? (g_w2l + (size_t)layer * CH * TWOH)
                                  : (g_w1l + (size_t)layer * TWOH * CH);

    __shared__ __nv_bfloat16 sAh[128 * SSTR];
    __shared__ __nv_bfloat16 sAl[128 * SSTR];
    __shared__ __nv_bfloat16 sBh[128 * SSTR];
    __shared__ __nv_bfloat16 sBl[128 * SSTR];

    int tid = threadIdx.x;
    int warp = tid >> 5, lane = tid & 31;
    int wm = warp & 1;        // 2 warps along M: 64 rows each
    int wn = warp >> 1;       // 4 warps along N: 32 cols each
    int row0 = blockIdx.x * 128;
    int col0 = blockIdx.y * 128;
    int g = lane >> 2, q = lane & 3;

    // LDSM lane->address components (element offsets within tile)
    int a_off = (wm * 64 + (lane & 7) + ((lane >> 3) & 1) * 8) * SSTR + (lane >> 4) * 8;
    int b_off = (wn * 32 + (lane & 7) + (lane >> 4) * 8) * SSTR + ((lane >> 3) & 1) * 8;

    uint32 sAh_u = (uint32)__cvta_generic_to_shared(sAh);
    uint32 sAl_u = (uint32)__cvta_generic_to_shared(sAl);
    uint32 sBh_u = (uint32)__cvta_generic_to_shared(sBh);
    uint32 sBl_u = (uint32)__cvta_generic_to_shared(sBl);

    float c[4][4][4];
    #pragma unroll
    for (int i = 0; i < 4; i++)
        #pragma unroll
        for (int j = 0; j < 4; j++)
            #pragma unroll
            for (int r = 0; r < 4; r++) c[i][j][r] = 0.f;

    // cp.async staging: thread handles 2 (row, 8-col) chunks per array per kk step
    int rr[2], rc[2];
    #pragma unroll
    for (int i = 0; i < 2; i++) {
        int idx = tid * 2 + i;
        rr[i] = idx >> 2;              // 0..127
        rc[i] = (idx & 3) * 8;         // 0,8,16,24 (uint4 = 8 bf16)
    }
    uint32 aok[2];
    #pragma unroll
    for (int i = 0; i < 2; i++) aok[i] = (row0 + rr[i] < NNODES) ? 16u : 0u;

    for (int kk = 0; kk < K; kk += 32) {
        #pragma unroll
        for (int i = 0; i < 2; i++) {
            uint32 soff = (uint32)(rr[i] * SSTR + rc[i]) * 2u;
            const __nv_bfloat16* gA = Ah + (size_t)(row0 + rr[i]) * K + kk + rc[i];
            const __nv_bfloat16* gAl2 = Al + (size_t)(row0 + rr[i]) * K + kk + rc[i];
            const __nv_bfloat16* gW = Wh + (size_t)(col0 + rr[i]) * K + kk + rc[i];
            const __nv_bfloat16* gWl2 = Wl + (size_t)(col0 + rr[i]) * K + kk + rc[i];
            cp16(sAh_u + soff, gA, aok[i]);
            cp16(sAl_u + soff, gAl2, aok[i]);
            cp16(sBh_u + soff, gW, 16u);
            cp16(sBl_u + soff, gWl2, 16u);
        }
        asm volatile("cp.async.commit_group;" ::: "memory");
        asm volatile("cp.async.wait_group 0;" ::: "memory");
        __syncthreads();

        #pragma unroll
        for (int ks = 0; ks < 32; ks += 16) {
            uint32 ah[4][4], al4[4][4], bh[4][2], bl4[4][2];
            #pragma unroll
            for (int mt = 0; mt < 4; mt++) {
                uint32 eoff = (uint32)(a_off + mt * 16 * SSTR + ks) * 2u;
                ldsm_x4(ah[mt][0], ah[mt][1], ah[mt][2], ah[mt][3], sAh_u + eoff);
                ldsm_x4(al4[mt][0], al4[mt][1], al4[mt][2], al4[mt][3], sAl_u + eoff);
            }
            #pragma unroll
            for (int p = 0; p < 2; p++) {
                uint32 eoff = (uint32)(b_off + p * 16 * SSTR + ks) * 2u;
                ldsm_x4(bh[2*p][0], bh[2*p][1], bh[2*p+1][0], bh[2*p+1][1], sBh_u + eoff);
                ldsm_x4(bl4[2*p][0], bl4[2*p][1], bl4[2*p+1][0], bl4[2*p+1][1], sBl_u + eoff);
            }
            #pragma unroll
            for (int mt = 0; mt < 4; mt++)
                #pragma unroll
                for (int nt = 0; nt < 4; nt++) {
                    mma_bf16(c[mt][nt], ah[mt], bh[nt]);
                    mma_bf16(c[mt][nt], ah[mt], bl4[nt]);
                    mma_bf16(c[mt][nt], al4[mt], bh[nt]);
                }
        }
        __syncthreads();
    }

    // epilogue: bias + BN + relu
    float sc[4][2], sh[4][2];
    #pragma unroll
    for (int nt = 0; nt < 4; nt++) {
        #pragma unroll
        for (int j = 0; j < 2; j++) {
            int col = col0 + wn * 32 + nt * 8 + 2 * q + j;
            float s = gam[col] * rsqrtf(var[col] + BN_EPS);
            sc[nt][j] = s;
            sh[nt][j] = bet[col] - mu[col] * s + bias[col] * s;
        }
    }
    #pragma unroll
    for (int mt = 0; mt < 4; mt++) {
        int r0 = row0 + wm * 64 + mt * 16 + g;
        int r1 = r0 + 8;
        #pragma unroll
        for (int nt = 0; nt < 4; nt++) {
            int col = col0 + wn * 32 + nt * 8 + 2 * q;
            float v00 = fmaxf(c[mt][nt][0] * sc[nt][0] + sh[nt][0], 0.f);
            float v01 = fmaxf(c[mt][nt][1] * sc[nt][1] + sh[nt][1], 0.f);
            float v10 = fmaxf(c[mt][nt][2] * sc[nt][0] + sh[nt][0], 0.f);
            float v11 = fmaxf(c[mt][nt][3] * sc[nt][1] + sh[nt][1], 0.f);
            if (SEL == 0) {
                if (r0 < NNODES) {
                    __nv_bfloat16 h0 = __float2bfloat16(v00), h1 = __float2bfloat16(v01);
                    *(__nv_bfloat162*)(g_bh + (size_t)r0 * TWOH + col) = __nv_bfloat162(h0, h1);
                    *(__nv_bfloat162*)(g_bl + (size_t)r0 * TWOH + col) =
                        __nv_bfloat162(__float2bfloat16(v00 - __bfloat162float(h0)),
                                       __float2bfloat16(v01 - __bfloat162float(h1)));
                }
                if (r1 < NNODES) {
                    __nv_bfloat16 h0 = __float2bfloat16(v10), h1 = __float2bfloat16(v11);
                    *(__nv_bfloat162*)(g_bh + (size_t)r1 * TWOH + col) = __nv_bfloat162(h0, h1);
                    *(__nv_bfloat162*)(g_bl + (size_t)r1 * TWOH + col) =
                        __nv_bfloat162(__float2bfloat16(v10 - __bfloat162float(h0)),
                                       __float2bfloat16(v11 - __bfloat162float(h1)));
                }
            } else {
                if (r0 < NNODES) *(float2*)(g_x + (size_t)r0 * CH + col) = make_float2(v00, v01);
                if (r1 < NNODES) *(float2*)(g_x + (size_t)r1 * CH + col) = make_float2(v10, v11);
            }
        }
    }
}

// ---------------- fused pool + readout head (one block per graph, 128 threads) ----------------
__global__ void k_pool_head(const int* __restrict__ batch,
                            const float* __restrict__ Wl1, const float* __restrict__ bl1,
                            const float* __restrict__ gb1, const float* __restrict__ bb1,
                            const float* __restrict__ mb1, const float* __restrict__ vb1,
                            const float* __restrict__ Wl2, const float* __restrict__ bl2,
                            float* __restrict__ out)
{
    int gr = blockIdx.x;
    int t = threadIdx.x;   // 0..127 = channel

    int lo = 0, hi = NNODES;
    while (lo < hi) { int m = (lo + hi) >> 1; if (batch[m] < gr) lo = m + 1; else hi = m; }
    int start = lo;
    hi = NNODES;
    while (lo < hi) { int m = (lo + hi) >> 1; if (batch[m] < gr + 1) lo = m + 1; else hi = m; }
    int end = lo;

    float s0 = 0.f, s1 = 0.f;
    int i = start;
    for (; i + 1 < end; i += 2) {
        s0 += g_x[(size_t)i * CH + t];
        s1 += g_x[(size_t)(i + 1) * CH + t];
    }
    if (i < end) s0 += g_x[(size_t)i * CH + t];
    float pval = s0 + s1;

    __shared__ float p[CH];
    __shared__ float hrow[CH];
    __shared__ float logits[OUTC];
    p[t] = pval;
    __syncthreads();

    float acc = 0.f;
    #pragma unroll 8
    for (int k = 0; k < CH; k++) acc += p[k] * Wl1[k * CH + t];
    acc += bl1[t];
    float s = gb1[t] * rsqrtf(vb1[t] + BN_EPS);
    acc = (acc - mb1[t]) * s + bb1[t];
    hrow[t] = fmaxf(acc, 0.f);
    __syncthreads();
    if (t < OUTC) {
        float a = 0.f;
        #pragma unroll 8
        for (int k = 0; k < CH; k++) a += hrow[k] * Wl2[k * OUTC + t];
        logits[t] = a + bl2[t];
    }
    __syncthreads();
    if (t == 0) {
        float mx = -1e30f;
        for (int j = 0; j < OUTC; j++) mx = fmaxf(mx, logits[j]);
        float se = 0.f;
        for (int j = 0; j < OUTC; j++) se += expf(logits[j] - mx);
        float lse = mx + logf(se);
        for (int j = 0; j < OUTC; j++) out[gr * OUTC + j] = logits[j] - lse;
    }
}

// ---------------- launch ----------------
extern "C" void kernel_launch(void* const* d_in, const int* in_sizes, int n_in,
                              void* d_out, int out_size)
{
    const float* x     = (const float*)d_in[0];
    const int*   ei    = (const int*)d_in[1];
    const int*   batch = (const int*)d_in[2];
    const float* W1  = (const float*)d_in[3];
    const float* b1  = (const float*)d_in[4];
    const float* g1  = (const float*)d_in[5];
    const float* be1 = (const float*)d_in[6];
    const float* m1  = (const float*)d_in[7];
    const float* v1  = (const float*)d_in[8];
    const float* W2  = (const float*)d_in[9];
    const float* b2  = (const float*)d_in[10];
    const float* gO  = (const float*)d_in[11];
    const float* bO  = (const float*)d_in[12];
    const float* mO  = (const float*)d_in[13];
    const float* vO  = (const float*)d_in[14];
    const float* Wl1 = (const float*)d_in[15];
    const float* bl1 = (const float*)d_in[16];
    const float* gb1 = (const float*)d_in[17];
    const float* bb1 = (const float*)d_in[18];
    const float* mb1 = (const float*)d_in[19];
    const float* vb1 = (const float*)d_in[20];
    const float* Wl2 = (const float*)d_in[21];
    const float* bl2 = (const float*)d_in[22];
    float* out = (float*)d_out;

    k_prep<<<(2 * NLAYERS * TWOH * CH + 255) / 256, 256>>>(W1, W2);
    k_fill<<<(NEDGES + 255) / 256, 256>>>(ei);

    const int NBM = (NNODES + 127) / 128;   // 391
    for (int l = 0; l < NLAYERS; l++) {
        if (l == 0) k_agg<1><<<(NNODES * 32 + 255) / 256, 256>>>(x);
        else        k_agg<0><<<(NNODES * 32 + 255) / 256, 256>>>(nullptr);
        k_mmagemm<CH, TWOH, 0><<<dim3(NBM, 2), 256>>>(
            l, b1 + l * TWOH, g1 + l * TWOH, be1 + l * TWOH,
            m1 + l * TWOH, v1 + l * TWOH);
        k_mmagemm<TWOH, CH, 1><<<dim3(NBM, 1), 256>>>(
            l, b2 + l * CH, gO + l * CH, bO + l * CH,
            mO + l * CH, vO + l * CH);
    }

    k_pool_head<<<NGRAPHS, CH>>>(batch, Wl1, bl1, gb1, bb1, mb1, vb1, Wl2, bl2, out);
}

// round 13
// speedup vs baseline: 1.2126x; 1.0708x over previous
#include <cuda_runtime.h>
#include <cuda_bf16.h>
#include <math.h>
#include <stdint.h>

typedef unsigned int uint32;

#define NNODES 50000
#define NEDGES 800000
#define CH 128
#define TWOH 256
#define NLAYERS 5
#define NGRAPHS 256
#define OUTC 10
#define BN_EPS 1e-5f
#define MAXDEG 96

// ---------------- scratch (static device memory; no allocations) ----------------
__device__ int   g_cur[NNODES];
__device__ int   g_srcBuck[(size_t)NNODES * MAXDEG];

__device__ __nv_bfloat16 g_ah[(size_t)NNODES * CH];    // GIN input (x+agg) hi
__device__ __nv_bfloat16 g_al[(size_t)NNODES * CH];    // lo
__device__ __nv_bfloat16 g_bh[(size_t)NNODES * TWOH];  // hidden (after MLP1) hi
__device__ __nv_bfloat16 g_bl[(size_t)NNODES * TWOH];  // lo
__device__ float g_x[(size_t)NNODES * CH];             // layer output fp32

// weights, transposed to [n][k] and split hi/lo
__device__ __nv_bfloat16 g_w1h[NLAYERS * TWOH * CH];   // [l][n=256][k=128]
__device__ __nv_bfloat16 g_w1l[NLAYERS * TWOH * CH];
__device__ __nv_bfloat16 g_w2h[NLAYERS * CH * TWOH];   // [l][n=128][k=256]
__device__ __nv_bfloat16 g_w2l[NLAYERS * CH * TWOH];

// ---------------- prep: zero bucket counters + transpose/split weights ----------------
__global__ void k_prep(const float* __restrict__ W1, const float* __restrict__ W2) {
    int t = blockIdx.x * blockDim.x + threadIdx.x;
    if (t < NNODES) g_cur[t] = 0;
    const int S = NLAYERS * TWOH * CH;
    if (t < S) {
        int l = t / (TWOH * CH);
        int r = t % (TWOH * CH);
        int n = r / CH;
        int k = r % CH;
        float v = W1[(size_t)l * CH * TWOH + (size_t)k * TWOH + n];
        __nv_bfloat16 h = __float2bfloat16(v);
        g_w1h[t] = h;
        g_w1l[t] = __float2bfloat16(v - __bfloat162float(h));
    } else if (t < 2 * S) {
        int t2 = t - S;
        int l = t2 / (CH * TWOH);
        int r = t2 % (CH * TWOH);
        int n = r / TWOH;
        int k = r % TWOH;
        float v = W2[(size_t)l * TWOH * CH + (size_t)k * CH + n];
        __nv_bfloat16 h = __float2bfloat16(v);
        g_w2h[t2] = h;
        g_w2l[t2] = __float2bfloat16(v - __bfloat162float(h));
    }
}

// ---------------- bucket scatter: one pass over edges ----------------
__global__ void k_fill(const int* __restrict__ ei) {
    int t = blockIdx.x * blockDim.x + threadIdx.x;
    if (t < NEDGES) {
        int s = ei[t];
        int d = ei[NEDGES + t];
        int pos = atomicAdd(&g_cur[d], 1);
        if (pos < MAXDEG) g_srcBuck[(size_t)d * MAXDEG + pos] = s;
    }
}

// ---------------- aggregation: one warp/node, fp32 accum, writes bf16 hi/lo ----------------
template<int USE_EXT>
__global__ void k_agg(const float* __restrict__ xext) {
    int warp = (blockIdx.x * blockDim.x + threadIdx.x) >> 5;
    int lane = threadIdx.x & 31;
    if (warp >= NNODES) return;
    const float* xin = USE_EXT ? xext : (const float*)g_x;
    int deg = g_cur[warp];
    if (deg > MAXDEG) deg = MAXDEG;
    const int* buck = g_srcBuck + (size_t)warp * MAXDEG;
    float4 acc = *((const float4*)(xin + (size_t)warp * CH) + lane);
    for (int e = 0; e < deg; e++) {
        int s = buck[e];
        float4 v = *((const float4*)(xin + (size_t)s * CH) + lane);
        acc.x += v.x; acc.y += v.y; acc.z += v.z; acc.w += v.w;
    }
    float vv[4] = {acc.x, acc.y, acc.z, acc.w};
    __nv_bfloat162 hp[2], lp[2];
    #pragma unroll
    for (int j = 0; j < 2; j++) {
        __nv_bfloat16 h0 = __float2bfloat16(vv[2*j]);
        __nv_bfloat16 h1 = __float2bfloat16(vv[2*j+1]);
        hp[j] = __nv_bfloat162(h0, h1);
        lp[j] = __nv_bfloat162(__float2bfloat16(vv[2*j]   - __bfloat162float(h0)),
                               __float2bfloat16(vv[2*j+1] - __bfloat162float(h1)));
    }
    __nv_bfloat162* ph = (__nv_bfloat162*)(g_ah + (size_t)warp * CH) + lane * 2;
    __nv_bfloat162* pl = (__nv_bfloat162*)(g_al + (size_t)warp * CH) + lane * 2;
    ph[0] = hp[0]; ph[1] = hp[1];
    pl[0] = lp[0]; pl[1] = lp[1];
}

// ---------------- tensor-core GEMM (bf16 split, fp32 accum) + bias/BN/ReLU ----------------
// 256 threads, 8 warps (2 M x 4 N); warp tile M64 x N32; block tile M128 x N128.
// Double-buffered dynamic smem (2 x 40KB) + cp.async; __launch_bounds__(256,2) -> 2 CTAs/SM.
#define SSTR 40   // smem row stride in bf16 (80 bytes): 16B-aligned & LDSM conflict-free
#define TILE_BYTES (128 * SSTR * 2)      // 10240 B per array
#define BUF_BYTES  (4 * TILE_BYTES)      // 40960 B per buffer (Ah, Al, Bh, Bl)

__device__ __forceinline__ void mma_bf16(float c[4], const uint32 a[4], const uint32 b[2]) {
    asm volatile(
        "mma.sync.aligned.m16n8k16.row.col.f32.bf16.bf16.f32 "
        "{%0,%1,%2,%3}, {%4,%5,%6,%7}, {%8,%9}, {%0,%1,%2,%3};"
        : "+f"(c[0]), "+f"(c[1]), "+f"(c[2]), "+f"(c[3])
        : "r"(a[0]), "r"(a[1]), "r"(a[2]), "r"(a[3]), "r"(b[0]), "r"(b[1]));
}

__device__ __forceinline__ void ldsm_x4(uint32& r0, uint32& r1, uint32& r2, uint32& r3, uint32 addr) {
    asm volatile("ldmatrix.sync.aligned.m8n8.x4.shared.b16 {%0,%1,%2,%3}, [%4];"
                 : "=r"(r0), "=r"(r1), "=r"(r2), "=r"(r3) : "r"(addr));
}

__device__ __forceinline__ void cp16(uint32 saddr, const void* gptr, uint32 src_sz) {
    asm volatile("cp.async.cg.shared.global [%0], [%1], 16, %2;"
                 :: "r"(saddr), "l"(gptr), "r"(src_sz) : "memory");
}

template<int K, int NCOL, int SEL>
__global__ void __launch_bounds__(256, 2)
k_mmagemm(int layer,
          const float* __restrict__ bias, const float* __restrict__ gam,
          const float* __restrict__ bet, const float* __restrict__ mu,
          const float* __restrict__ var)
{
    const __nv_bfloat16* Ah = SEL ? g_bh : g_ah;
    const __nv_bfloat16* Al = SEL ? g_bl : g_al;
    const __nv_bfloat16* Wh = SEL ? (g_w2h + (size_t)layer * CH * TWOH)
                                  : (g_w1h + (size_t)layer * TWOH * CH);
    const __nv_bfloat16* Wl = SEL ? (g_w2l + (size_t)layer * CH * TWOH)
                                  : (g_w1l + (size_t)layer * TWOH * CH);

    extern __shared__ char smem[];
    uint32 smem_u = (uint32)__cvta_generic_to_shared(smem);

    int tid = threadIdx.x;
    int warp = tid >> 5, lane = tid & 31;
    int wm = warp & 1;        // 2 warps along M: 64 rows each
    int wn = warp >> 1;       // 4 warps along N: 32 cols each
    int row0 = blockIdx.x * 128;
    int col0 = blockIdx.y * 128;
    int g = lane >> 2, q = lane & 3;

    // LDSM lane->address components (byte offsets within an array tile)
    uint32 a_off = (uint32)((wm * 64 + (lane & 7) + ((lane >> 3) & 1) * 8) * SSTR + (lane >> 4) * 8) * 2u;
    uint32 b_off = (uint32)((wn * 32 + (lane & 7) + (lane >> 4) * 8) * SSTR + ((lane >> 3) & 1) * 8) * 2u;

    float c[4][4][4];
    #pragma unroll
    for (int i = 0; i < 4; i++)
        #pragma unroll
        for (int j = 0; j < 4; j++)
            #pragma unroll
            for (int r = 0; r < 4; r++) c[i][j][r] = 0.f;

    // cp.async staging: thread handles 2 (row, 8-col) chunks per array per kk step
    int rr[2], rc[2];
    uint32 aok[2], soff[2];
    #pragma unroll
    for (int i = 0; i < 2; i++) {
        int idx = tid * 2 + i;
        rr[i] = idx >> 2;              // 0..127
        rc[i] = (idx & 3) * 8;         // 0,8,16,24 (uint4 = 8 bf16)
        aok[i] = (row0 + rr[i] < NNODES) ? 16u : 0u;
        soff[i] = (uint32)(rr[i] * SSTR + rc[i]) * 2u;
    }

    auto issue = [&](int kk, uint32 base) {
        #pragma unroll
        for (int i = 0; i < 2; i++) {
            cp16(base + soff[i],                  Ah + (size_t)(row0 + rr[i]) * K + kk + rc[i], aok[i]);
            cp16(base + TILE_BYTES + soff[i],     Al + (size_t)(row0 + rr[i]) * K + kk + rc[i], aok[i]);
            cp16(base + 2 * TILE_BYTES + soff[i], Wh + (size_t)(col0 + rr[i]) * K + kk + rc[i], 16u);
            cp16(base + 3 * TILE_BYTES + soff[i], Wl + (size_t)(col0 + rr[i]) * K + kk + rc[i], 16u);
        }
        asm volatile("cp.async.commit_group;" ::: "memory");
    };

    constexpr int NITER = K / 32;
    issue(0, smem_u);
    #pragma unroll
    for (int it = 0; it < NITER; it++) {
        uint32 cur = smem_u + (uint32)(it & 1) * BUF_BYTES;
        if (it + 1 < NITER) {
            uint32 nxt = smem_u + (uint32)((it + 1) & 1) * BUF_BYTES;
            issue((it + 1) * 32, nxt);
            asm volatile("cp.async.wait_group 1;" ::: "memory");
        } else {
            asm volatile("cp.async.wait_group 0;" ::: "memory");
        }
        __syncthreads();

        uint32 sA = cur, sAl2 = cur + TILE_BYTES, sB = cur + 2 * TILE_BYTES, sBl2 = cur + 3 * TILE_BYTES;
        #pragma unroll
        for (int ks = 0; ks < 32; ks += 16) {
            uint32 ah[4][4], al4[4][4], bh[4][2], bl4[4][2];
            #pragma unroll
            for (int mt = 0; mt < 4; mt++) {
                uint32 eoff = a_off + (uint32)(mt * 16 * SSTR + ks) * 2u;
                ldsm_x4(ah[mt][0], ah[mt][1], ah[mt][2], ah[mt][3], sA + eoff);
                ldsm_x4(al4[mt][0], al4[mt][1], al4[mt][2], al4[mt][3], sAl2 + eoff);
            }
            #pragma unroll
            for (int p = 0; p < 2; p++) {
                uint32 eoff = b_off + (uint32)(p * 16 * SSTR + ks) * 2u;
                ldsm_x4(bh[2*p][0], bh[2*p][1], bh[2*p+1][0], bh[2*p+1][1], sB + eoff);
                ldsm_x4(bl4[2*p][0], bl4[2*p][1], bl4[2*p+1][0], bl4[2*p+1][1], sBl2 + eoff);
            }
            #pragma unroll
            for (int mt = 0; mt < 4; mt++)
                #pragma unroll
                for (int nt = 0; nt < 4; nt++) {
                    mma_bf16(c[mt][nt], ah[mt], bh[nt]);
                    mma_bf16(c[mt][nt], ah[mt], bl4[nt]);
                    mma_bf16(c[mt][nt], al4[mt], bh[nt]);
                }
        }
        __syncthreads();
    }

    // epilogue: bias + BN + relu
    float sc[4][2], sh[4][2];
    #pragma unroll
    for (int nt = 0; nt < 4; nt++) {
        #pragma unroll
        for (int j = 0; j < 2; j++) {
            int col = col0 + wn * 32 + nt * 8 + 2 * q + j;
            float s = gam[col] * rsqrtf(var[col] + BN_EPS);
            sc[nt][j] = s;
            sh[nt][j] = bet[col] - mu[col] * s + bias[col] * s;
        }
    }
    #pragma unroll
    for (int mt = 0; mt < 4; mt++) {
        int r0 = row0 + wm * 64 + mt * 16 + g;
        int r1 = r0 + 8;
        #pragma unroll
        for (int nt = 0; nt < 4; nt++) {
            int col = col0 + wn * 32 + nt * 8 + 2 * q;
            float v00 = fmaxf(c[mt][nt][0] * sc[nt][0] + sh[nt][0], 0.f);
            float v01 = fmaxf(c[mt][nt][1] * sc[nt][1] + sh[nt][1], 0.f);
            float v10 = fmaxf(c[mt][nt][2] * sc[nt][0] + sh[nt][0], 0.f);
            float v11 = fmaxf(c[mt][nt][3] * sc[nt][1] + sh[nt][1], 0.f);
            if (SEL == 0) {
                if (r0 < NNODES) {
                    __nv_bfloat16 h0 = __float2bfloat16(v00), h1 = __float2bfloat16(v01);
                    *(__nv_bfloat162*)(g_bh + (size_t)r0 * TWOH + col) = __nv_bfloat162(h0, h1);
                    *(__nv_bfloat162*)(g_bl + (size_t)r0 * TWOH + col) =
                        __nv_bfloat162(__float2bfloat16(v00 - __bfloat162float(h0)),
                                       __float2bfloat16(v01 - __bfloat162float(h1)));
                }
                if (r1 < NNODES) {
                    __nv_bfloat16 h0 = __float2bfloat16(v10), h1 = __float2bfloat16(v11);
                    *(__nv_bfloat162*)(g_bh + (size_t)r1 * TWOH + col) = __nv_bfloat162(h0, h1);
                    *(__nv_bfloat162*)(g_bl + (size_t)r1 * TWOH + col) =
                        __nv_bfloat162(__float2bfloat16(v10 - __bfloat162float(h0)),
                                       __float2bfloat16(v11 - __bfloat162float(h1)));
                }
            } else {
                if (r0 < NNODES) *(float2*)(g_x + (size_t)r0 * CH + col) = make_float2(v00, v01);
                if (r1 < NNODES) *(float2*)(g_x + (size_t)r1 * CH + col) = make_float2(v10, v11);
            }
        }
    }
}

// ---------------- fused pool + readout head (one block per graph, 128 threads) ----------------
__global__ void k_pool_head(const int* __restrict__ batch,
                            const float* __restrict__ Wl1, const float* __restrict__ bl1,
                            const float* __restrict__ gb1, const float* __restrict__ bb1,
                            const float* __restrict__ mb1, const float* __restrict__ vb1,
                            const float* __restrict__ Wl2, const float* __restrict__ bl2,
                            float* __restrict__ out)
{
    int gr = blockIdx.x;
    int t = threadIdx.x;   // 0..127 = channel

    int lo = 0, hi = NNODES;
    while (lo < hi) { int m = (lo + hi) >> 1; if (batch[m] < gr) lo = m + 1; else hi = m; }
    int start = lo;
    hi = NNODES;
    while (lo < hi) { int m = (lo + hi) >> 1; if (batch[m] < gr + 1) lo = m + 1; else hi = m; }
    int end = lo;

    float s0 = 0.f, s1 = 0.f;
    int i = start;
    for (; i + 1 < end; i += 2) {
        s0 += g_x[(size_t)i * CH + t];
        s1 += g_x[(size_t)(i + 1) * CH + t];
    }
    if (i < end) s0 += g_x[(size_t)i * CH + t];
    float pval = s0 + s1;

    __shared__ float p[CH];
    __shared__ float hrow[CH];
    __shared__ float logits[OUTC];
    p[t] = pval;
    __syncthreads();

    float acc = 0.f;
    #pragma unroll 8
    for (int k = 0; k < CH; k++) acc += p[k] * Wl1[k * CH + t];
    acc += bl1[t];
    float s = gb1[t] * rsqrtf(vb1[t] + BN_EPS);
    acc = (acc - mb1[t]) * s + bb1[t];
    hrow[t] = fmaxf(acc, 0.f);
    __syncthreads();
    if (t < OUTC) {
        float a = 0.f;
        #pragma unroll 8
        for (int k = 0; k < CH; k++) a += hrow[k] * Wl2[k * OUTC + t];
        logits[t] = a + bl2[t];
    }
    __syncthreads();
    if (t == 0) {
        float mx = -1e30f;
        for (int j = 0; j < OUTC; j++) mx = fmaxf(mx, logits[j]);
        float se = 0.f;
        for (int j = 0; j < OUTC; j++) se += expf(logits[j] - mx);
        float lse = mx + logf(se);
        for (int j = 0; j < OUTC; j++) out[gr * OUTC + j] = logits[j] - lse;
    }
}

// ---------------- launch ----------------
extern "C" void kernel_launch(void* const* d_in, const int* in_sizes, int n_in,
                              void* d_out, int out_size)
{
    const float* x     = (const float*)d_in[0];
    const int*   ei    = (const int*)d_in[1];
    const int*   batch = (const int*)d_in[2];
    const float* W1  = (const float*)d_in[3];
    const float* b1  = (const float*)d_in[4];
    const float* g1  = (const float*)d_in[5];
    const float* be1 = (const float*)d_in[6];
    const float* m1  = (const float*)d_in[7];
    const float* v1  = (const float*)d_in[8];
    const float* W2  = (const float*)d_in[9];
    const float* b2  = (const float*)d_in[10];
    const float* gO  = (const float*)d_in[11];
    const float* bO  = (const float*)d_in[12];
    const float* mO  = (const float*)d_in[13];
    const float* vO  = (const float*)d_in[14];
    const float* Wl1 = (const float*)d_in[15];
    const float* bl1 = (const float*)d_in[16];
    const float* gb1 = (const float*)d_in[17];
    const float* bb1 = (const float*)d_in[18];
    const float* mb1 = (const float*)d_in[19];
    const float* vb1 = (const float*)d_in[20];
    const float* Wl2 = (const float*)d_in[21];
    const float* bl2 = (const float*)d_in[22];
    float* out = (float*)d_out;

    const int DSMEM = 2 * BUF_BYTES;   // 81920
    static int smem_set = 0;
    if (!smem_set) {
        cudaFuncSetAttribute(k_mmagemm<CH, TWOH, 0>, cudaFuncAttributeMaxDynamicSharedMemorySize, DSMEM);
        cudaFuncSetAttribute(k_mmagemm<TWOH, CH, 1>, cudaFuncAttributeMaxDynamicSharedMemorySize, DSMEM);
        smem_set = 1;
    }

    k_prep<<<(2 * NLAYERS * TWOH * CH + 255) / 256, 256>>>(W1, W2);
    k_fill<<<(NEDGES + 255) / 256, 256>>>(ei);

    const int NBM = (NNODES + 127) / 128;   // 391
    for (int l = 0; l < NLAYERS; l++) {
        if (l == 0) k_agg<1><<<(NNODES * 32 + 255) / 256, 256>>>(x);
        else        k_agg<0><<<(NNODES * 32 + 255) / 256, 256>>>(nullptr);
        k_mmagemm<CH, TWOH, 0><<<dim3(NBM, 2), 256, DSMEM>>>(
            l, b1 + l * TWOH, g1 + l * TWOH, be1 + l * TWOH,
            m1 + l * TWOH, v1 + l * TWOH);
        k_mmagemm<TWOH, CH, 1><<<dim3(NBM, 1), 256, DSMEM>>>(
            l, b2 + l * CH, gO + l * CH, bO + l * CH,
            mO + l * CH, vO + l * CH);
    }

    k_pool_head<<<NGRAPHS, CH>>>(batch, Wl1, bl1, gb1, bb1, mb1, vb1, Wl2, bl2, out);
}

// round 14
// speedup vs baseline: 1.2999x; 1.0720x over previous
#include <cuda_runtime.h>
#include <cuda_bf16.h>
#include <math.h>
#include <stdint.h>

typedef unsigned int uint32;

#define NNODES 50000
#define NEDGES 800000
#define CH 128
#define TWOH 256
#define NLAYERS 5
#define NGRAPHS 256
#define OUTC 10
#define BN_EPS 1e-5f
#define MAXDEG 96

// ---------------- scratch (static device memory; no allocations) ----------------
__device__ int   g_cur[NNODES];
__device__ int   g_srcBuck[(size_t)NNODES * MAXDEG];

__device__ __nv_bfloat16 g_ah[(size_t)NNODES * CH];    // GIN input (x+agg) hi
__device__ __nv_bfloat16 g_al[(size_t)NNODES * CH];    // lo
__device__ __nv_bfloat16 g_bh[(size_t)NNODES * TWOH];  // hidden (after MLP1) hi
__device__ __nv_bfloat16 g_bl[(size_t)NNODES * TWOH];  // lo
__device__ float g_x[(size_t)NNODES * CH];             // layer output fp32

// weights, transposed to [n][k] and split hi/lo
__device__ __nv_bfloat16 g_w1h[NLAYERS * TWOH * CH];   // [l][n=256][k=128]
__device__ __nv_bfloat16 g_w1l[NLAYERS * TWOH * CH];
__device__ __nv_bfloat16 g_w2h[NLAYERS * CH * TWOH];   // [l][n=128][k=256]
__device__ __nv_bfloat16 g_w2l[NLAYERS * CH * TWOH];

// ---------------- prep: zero bucket counters + transpose/split weights ----------------
__global__ void k_prep(const float* __restrict__ W1, const float* __restrict__ W2) {
    int t = blockIdx.x * blockDim.x + threadIdx.x;
    if (t < NNODES) g_cur[t] = 0;
    const int S = NLAYERS * TWOH * CH;
    if (t < S) {
        int l = t / (TWOH * CH);
        int r = t % (TWOH * CH);
        int n = r / CH;
        int k = r % CH;
        float v = W1[(size_t)l * CH * TWOH + (size_t)k * TWOH + n];
        __nv_bfloat16 h = __float2bfloat16(v);
        g_w1h[t] = h;
        g_w1l[t] = __float2bfloat16(v - __bfloat162float(h));
    } else if (t < 2 * S) {
        int t2 = t - S;
        int l = t2 / (CH * TWOH);
        int r = t2 % (CH * TWOH);
        int n = r / TWOH;
        int k = r % TWOH;
        float v = W2[(size_t)l * TWOH * CH + (size_t)k * CH + n];
        __nv_bfloat16 h = __float2bfloat16(v);
        g_w2h[t2] = h;
        g_w2l[t2] = __float2bfloat16(v - __bfloat162float(h));
    }
}

// ---------------- bucket scatter: one pass over edges ----------------
__global__ void k_fill(const int* __restrict__ ei) {
    int t = blockIdx.x * blockDim.x + threadIdx.x;
    if (t < NEDGES) {
        int s = ei[t];
        int d = ei[NEDGES + t];
        int pos = atomicAdd(&g_cur[d], 1);
        if (pos < MAXDEG) g_srcBuck[(size_t)d * MAXDEG + pos] = s;
    }
}

// ---------------- aggregation: one warp/node, fp32 accum, writes bf16 hi/lo ----------------
template<int USE_EXT>
__global__ void k_agg(const float* __restrict__ xext) {
    int warp = (blockIdx.x * blockDim.x + threadIdx.x) >> 5;
    int lane = threadIdx.x & 31;
    if (warp >= NNODES) return;
    const float* xin = USE_EXT ? xext : (const float*)g_x;
    int deg = g_cur[warp];
    if (deg > MAXDEG) deg = MAXDEG;
    const int* buck = g_srcBuck + (size_t)warp * MAXDEG;
    float4 acc = *((const float4*)(xin + (size_t)warp * CH) + lane);
    for (int e = 0; e < deg; e++) {
        int s = buck[e];
        float4 v = *((const float4*)(xin + (size_t)s * CH) + lane);
        acc.x += v.x; acc.y += v.y; acc.z += v.z; acc.w += v.w;
    }
    float vv[4] = {acc.x, acc.y, acc.z, acc.w};
    __nv_bfloat162 hp[2], lp[2];
    #pragma unroll
    for (int j = 0; j < 2; j++) {
        __nv_bfloat16 h0 = __float2bfloat16(vv[2*j]);
        __nv_bfloat16 h1 = __float2bfloat16(vv[2*j+1]);
        hp[j] = __nv_bfloat162(h0, h1);
        lp[j] = __nv_bfloat162(__float2bfloat16(vv[2*j]   - __bfloat162float(h0)),
                               __float2bfloat16(vv[2*j+1] - __bfloat162float(h1)));
    }
    __nv_bfloat162* ph = (__nv_bfloat162*)(g_ah + (size_t)warp * CH) + lane * 2;
    __nv_bfloat162* pl = (__nv_bfloat162*)(g_al + (size_t)warp * CH) + lane * 2;
    ph[0] = hp[0]; ph[1] = hp[1];
    pl[0] = lp[0]; pl[1] = lp[1];
}

// ---------------- tensor-core GEMM (bf16 split, fp32 accum) + bias/BN/ReLU ----------------
// 256 threads, 8 warps (2 M x 4 N); block tile MTILE x 128; warp tile (MTILE/2) x 32.
// Double-buffered dynamic smem + cp.async. MAXCTA CTAs/SM via launch_bounds.
#define SSTR 40   // smem row stride in bf16 (80 bytes): 16B-aligned & LDSM conflict-free

__device__ __forceinline__ void mma_bf16(float c[4], const uint32 a[4], const uint32 b[2]) {
    asm volatile(
        "mma.sync.aligned.m16n8k16.row.col.f32.bf16.bf16.f32 "
        "{%0,%1,%2,%3}, {%4,%5,%6,%7}, {%8,%9}, {%0,%1,%2,%3};"
        : "+f"(c[0]), "+f"(c[1]), "+f"(c[2]), "+f"(c[3])
        : "r"(a[0]), "r"(a[1]), "r"(a[2]), "r"(a[3]), "r"(b[0]), "r"(b[1]));
}

__device__ __forceinline__ void ldsm_x4(uint32& r0, uint32& r1, uint32& r2, uint32& r3, uint32 addr) {
    asm volatile("ldmatrix.sync.aligned.m8n8.x4.shared.b16 {%0,%1,%2,%3}, [%4];"
                 : "=r"(r0), "=r"(r1), "=r"(r2), "=r"(r3) : "r"(addr));
}

__device__ __forceinline__ void cp16(uint32 saddr, const void* gptr, uint32 src_sz) {
    asm volatile("cp.async.cg.shared.global [%0], [%1], 16, %2;"
                 :: "r"(saddr), "l"(gptr), "r"(src_sz) : "memory");
}

template<int K, int NCOL, int MTILE, int SEL, int MAXCTA>
__global__ void __launch_bounds__(256, MAXCTA)
k_mmagemm(int layer,
          const float* __restrict__ bias, const float* __restrict__ gam,
          const float* __restrict__ bet, const float* __restrict__ mu,
          const float* __restrict__ var)
{
    constexpr int MT = MTILE / 32;                 // m16-tiles per warp (4 or 2)
    constexpr int ATB = MTILE * SSTR * 2;          // bytes per A array tile
    constexpr int BTB = 128 * SSTR * 2;            // bytes per B array tile
    constexpr int BUFB = 2 * ATB + 2 * BTB;        // bytes per buffer

    const __nv_bfloat16* Ah = SEL ? g_bh : g_ah;
    const __nv_bfloat16* Al = SEL ? g_bl : g_al;
    const __nv_bfloat16* Wh = SEL ? (g_w2h + (size_t)layer * CH * TWOH)
                                  : (g_w1h + (size_t)layer * TWOH * CH);
    const __nv_bfloat16* Wl = SEL ? (g_w2l + (size_t)layer * CH * TWOH)
                                  : (g_w1l + (size_t)layer * TWOH * CH);

    extern __shared__ char smem[];
    uint32 smem_u = (uint32)__cvta_generic_to_shared(smem);
    __shared__ float s_sc[128], s_sh[128];

    int tid = threadIdx.x;
    int warp = tid >> 5, lane = tid & 31;
    int wm = warp & 1;        // 2 warps along M
    int wn = warp >> 1;       // 4 warps along N: 32 cols each
    int row0 = blockIdx.x * MTILE;
    int col0 = blockIdx.y * 128;
    int g = lane >> 2, q = lane & 3;

    // LDSM lane->address components (byte offsets within an array tile)
    uint32 a_off = (uint32)((wm * (MTILE / 2) + (lane & 7) + ((lane >> 3) & 1) * 8) * SSTR + (lane >> 4) * 8) * 2u;
    uint32 b_off = (uint32)((wn * 32 + (lane & 7) + (lane >> 4) * 8) * SSTR + ((lane >> 3) & 1) * 8) * 2u;

    float c[MT][4][4];
    #pragma unroll
    for (int i = 0; i < MT; i++)
        #pragma unroll
        for (int j = 0; j < 4; j++)
            #pragma unroll
            for (int r = 0; r < 4; r++) c[i][j][r] = 0.f;

    auto issue = [&](int kk, uint32 base) {
        #pragma unroll
        for (int ii = 0; ii < MTILE * 4 / 256; ii++) {
            int idx = tid + ii * 256;
            int r = idx >> 2, c8 = (idx & 3) * 8;
            uint32 ok = (row0 + r < NNODES) ? 16u : 0u;
            uint32 soff = (uint32)(r * SSTR + c8) * 2u;
            cp16(base + soff,       Ah + (size_t)(row0 + r) * K + kk + c8, ok);
            cp16(base + ATB + soff, Al + (size_t)(row0 + r) * K + kk + c8, ok);
        }
        #pragma unroll
        for (int ii = 0; ii < 2; ii++) {
            int idx = tid + ii * 256;
            int r = idx >> 2, c8 = (idx & 3) * 8;
            uint32 soff = (uint32)(r * SSTR + c8) * 2u;
            cp16(base + 2 * ATB + soff,       Wh + (size_t)(col0 + r) * K + kk + c8, 16u);
            cp16(base + 2 * ATB + BTB + soff, Wl + (size_t)(col0 + r) * K + kk + c8, 16u);
        }
        asm volatile("cp.async.commit_group;" ::: "memory");
    };

    issue(0, smem_u);
    // BN fold into smem (overlaps first load)
    if (tid < 128) {
        int col = col0 + tid;
        float s = gam[col] * rsqrtf(var[col] + BN_EPS);
        s_sc[tid] = s;
        s_sh[tid] = bet[col] - mu[col] * s + bias[col] * s;
    }

    constexpr int NITER = K / 32;
    #pragma unroll
    for (int it = 0; it < NITER; it++) {
        uint32 cur = smem_u + (uint32)(it & 1) * BUFB;
        if (it + 1 < NITER) {
            uint32 nxt = smem_u + (uint32)((it + 1) & 1) * BUFB;
            issue((it + 1) * 32, nxt);
            asm volatile("cp.async.wait_group 1;" ::: "memory");
        } else {
            asm volatile("cp.async.wait_group 0;" ::: "memory");
        }
        __syncthreads();

        uint32 sA = cur, sAl2 = cur + ATB, sB = cur + 2 * ATB, sBl2 = cur + 2 * ATB + BTB;
        #pragma unroll
        for (int ks = 0; ks < 32; ks += 16) {
            uint32 ah[MT][4], al4[MT][4], bh[4][2], bl4[4][2];
            #pragma unroll
            for (int mt = 0; mt < MT; mt++) {
                uint32 eoff = a_off + (uint32)(mt * 16 * SSTR + ks) * 2u;
                ldsm_x4(ah[mt][0], ah[mt][1], ah[mt][2], ah[mt][3], sA + eoff);
                ldsm_x4(al4[mt][0], al4[mt][1], al4[mt][2], al4[mt][3], sAl2 + eoff);
            }
            #pragma unroll
            for (int p = 0; p < 2; p++) {
                uint32 eoff = b_off + (uint32)(p * 16 * SSTR + ks) * 2u;
                ldsm_x4(bh[2*p][0], bh[2*p][1], bh[2*p+1][0], bh[2*p+1][1], sB + eoff);
                ldsm_x4(bl4[2*p][0], bl4[2*p][1], bl4[2*p+1][0], bl4[2*p+1][1], sBl2 + eoff);
            }
            #pragma unroll
            for (int mt = 0; mt < MT; mt++)
                #pragma unroll
                for (int nt = 0; nt < 4; nt++) {
                    mma_bf16(c[mt][nt], ah[mt], bh[nt]);
                    mma_bf16(c[mt][nt], ah[mt], bl4[nt]);
                    mma_bf16(c[mt][nt], al4[mt], bh[nt]);
                }
        }
        __syncthreads();
    }

    // epilogue: bias + BN + relu (scale/shift from smem)
    #pragma unroll
    for (int mt = 0; mt < MT; mt++) {
        int r0 = row0 + wm * (MTILE / 2) + mt * 16 + g;
        int r1 = r0 + 8;
        #pragma unroll
        for (int nt = 0; nt < 4; nt++) {
            int lc = wn * 32 + nt * 8 + 2 * q;      // block-local col
            int col = col0 + lc;
            float sc0 = s_sc[lc],     sh0 = s_sh[lc];
            float sc1 = s_sc[lc + 1], sh1 = s_sh[lc + 1];
            float v00 = fmaxf(c[mt][nt][0] * sc0 + sh0, 0.f);
            float v01 = fmaxf(c[mt][nt][1] * sc1 + sh1, 0.f);
            float v10 = fmaxf(c[mt][nt][2] * sc0 + sh0, 0.f);
            float v11 = fmaxf(c[mt][nt][3] * sc1 + sh1, 0.f);
            if (SEL == 0) {
                if (r0 < NNODES) {
                    __nv_bfloat16 h0 = __float2bfloat16(v00), h1 = __float2bfloat16(v01);
                    *(__nv_bfloat162*)(g_bh + (size_t)r0 * TWOH + col) = __nv_bfloat162(h0, h1);
                    *(__nv_bfloat162*)(g_bl + (size_t)r0 * TWOH + col) =
                        __nv_bfloat162(__float2bfloat16(v00 - __bfloat162float(h0)),
                                       __float2bfloat16(v01 - __bfloat162float(h1)));
                }
                if (r1 < NNODES) {
                    __nv_bfloat16 h0 = __float2bfloat16(v10), h1 = __float2bfloat16(v11);
                    *(__nv_bfloat162*)(g_bh + (size_t)r1 * TWOH + col) = __nv_bfloat162(h0, h1);
                    *(__nv_bfloat162*)(g_bl + (size_t)r1 * TWOH + col) =
                        __nv_bfloat162(__float2bfloat16(v10 - __bfloat162float(h0)),
                                       __float2bfloat16(v11 - __bfloat162float(h1)));
                }
            } else {
                if (r0 < NNODES) *(float2*)(g_x + (size_t)r0 * CH + col) = make_float2(v00, v01);
                if (r1 < NNODES) *(float2*)(g_x + (size_t)r1 * CH + col) = make_float2(v10, v11);
            }
        }
    }
}

// ---------------- fused pool + readout head (one block per graph, 128 threads) ----------------
__global__ void k_pool_head(const int* __restrict__ batch,
                            const float* __restrict__ Wl1, const float* __restrict__ bl1,
                            const float* __restrict__ gb1, const float* __restrict__ bb1,
                            const float* __restrict__ mb1, const float* __restrict__ vb1,
                            const float* __restrict__ Wl2, const float* __restrict__ bl2,
                            float* __restrict__ out)
{
    int gr = blockIdx.x;
    int t = threadIdx.x;   // 0..127 = channel

    int lo = 0, hi = NNODES;
    while (lo < hi) { int m = (lo + hi) >> 1; if (batch[m] < gr) lo = m + 1; else hi = m; }
    int start = lo;
    hi = NNODES;
    while (lo < hi) { int m = (lo + hi) >> 1; if (batch[m] < gr + 1) lo = m + 1; else hi = m; }
    int end = lo;

    float s0 = 0.f, s1 = 0.f;
    int i = start;
    for (; i + 1 < end; i += 2) {
        s0 += g_x[(size_t)i * CH + t];
        s1 += g_x[(size_t)(i + 1) * CH + t];
    }
    if (i < end) s0 += g_x[(size_t)i * CH + t];
    float pval = s0 + s1;

    __shared__ float p[CH];
    __shared__ float hrow[CH];
    __shared__ float logits[OUTC];
    p[t] = pval;
    __syncthreads();

    float acc = 0.f;
    #pragma unroll 8
    for (int k = 0; k < CH; k++) acc += p[k] * Wl1[k * CH + t];
    acc += bl1[t];
    float s = gb1[t] * rsqrtf(vb1[t] + BN_EPS);
    acc = (acc - mb1[t]) * s + bb1[t];
    hrow[t] = fmaxf(acc, 0.f);
    __syncthreads();
    if (t < OUTC) {
        float a = 0.f;
        #pragma unroll 8
        for (int k = 0; k < CH; k++) a += hrow[k] * Wl2[k * OUTC + t];
        logits[t] = a + bl2[t];
    }
    __syncthreads();
    if (t == 0) {
        float mx = -1e30f;
        for (int j = 0; j < OUTC; j++) mx = fmaxf(mx, logits[j]);
        float se = 0.f;
        for (int j = 0; j < OUTC; j++) se += expf(logits[j] - mx);
        float lse = mx + logf(se);
        for (int j = 0; j < OUTC; j++) out[gr * OUTC + j] = logits[j] - lse;
    }
}

// ---------------- launch ----------------
extern "C" void kernel_launch(void* const* d_in, const int* in_sizes, int n_in,
                              void* d_out, int out_size)
{
    const float* x     = (const float*)d_in[0];
    const int*   ei    = (const int*)d_in[1];
    const int*   batch = (const int*)d_in[2];
    const float* W1  = (const float*)d_in[3];
    const float* b1  = (const float*)d_in[4];
    const float* g1  = (const float*)d_in[5];
    const float* be1 = (const float*)d_in[6];
    const float* m1  = (const float*)d_in[7];
    const float* v1  = (const float*)d_in[8];
    const float* W2  = (const float*)d_in[9];
    const float* b2  = (const float*)d_in[10];
    const float* gO  = (const float*)d_in[11];
    const float* bO  = (const float*)d_in[12];
    const float* mO  = (const float*)d_in[13];
    const float* vO  = (const float*)d_in[14];
    const float* Wl1 = (const float*)d_in[15];
    const float* bl1 = (const float*)d_in[16];
    const float* gb1 = (const float*)d_in[17];
    const float* bb1 = (const float*)d_in[18];
    const float* mb1 = (const float*)d_in[19];
    const float* vb1 = (const float*)d_in[20];
    const float* Wl2 = (const float*)d_in[21];
    const float* bl2 = (const float*)d_in[22];
    float* out = (float*)d_out;

    // buffer sizes: per-buffer = 2*A + 2*B tiles
    const int DSMEM1 = 2 * (2 * (128 * SSTR * 2) + 2 * (128 * SSTR * 2));  // 81920
    const int DSMEM2 = 2 * (2 * (64 * SSTR * 2) + 2 * (128 * SSTR * 2));   // 61440
    static int smem_set = 0;
    if (!smem_set) {
        cudaFuncSetAttribute(k_mmagemm<CH, TWOH, 128, 0, 2>, cudaFuncAttributeMaxDynamicSharedMemorySize, DSMEM1);
        cudaFuncSetAttribute(k_mmagemm<TWOH, CH, 64, 1, 3>, cudaFuncAttributeMaxDynamicSharedMemorySize, DSMEM2);
        smem_set = 1;
    }

    k_prep<<<(2 * NLAYERS * TWOH * CH + 255) / 256, 256>>>(W1, W2);
    k_fill<<<(NEDGES + 255) / 256, 256>>>(ei);

    const int NBM1 = (NNODES + 127) / 128;   // 391
    const int NBM2 = (NNODES + 63) / 64;     // 782
    for (int l = 0; l < NLAYERS; l++) {
        if (l == 0) k_agg<1><<<(NNODES * 32 + 255) / 256, 256>>>(x);
        else        k_agg<0><<<(NNODES * 32 + 255) / 256, 256>>>(nullptr);
        k_mmagemm<CH, TWOH, 128, 0, 2><<<dim3(NBM1, 2), 256, DSMEM1>>>(
            l, b1 + l * TWOH, g1 + l * TWOH, be1 + l * TWOH,
            m1 + l * TWOH, v1 + l * TWOH);
        k_mmagemm<TWOH, CH, 64, 1, 3><<<dim3(NBM2, 1), 256, DSMEM2>>>(
            l, b2 + l * CH, gO + l * CH, bO + l * CH,
            mO + l * CH, vO + l * CH);
    }

    k_pool_head<<<NGRAPHS, CH>>>(batch, Wl1, bl1, gb1, bb1, mb1, vb1, Wl2, bl2, out);
}